// round 1
// baseline (speedup 1.0000x reference)
#include <cuda_runtime.h>

#define N_NODES 100000
#define N_EDGES 1000000
#define D 64

// ---------------- scratch (device globals; no runtime allocation) ----------
__device__ float4 g_agg4[N_NODES * D / 4];   // neighbor feature sums
__device__ float4 g_h4[N_NODES * D / 4];     // layer-1 hidden output
__device__ float  g_deg[N_NODES];            // in-degree (float, exact for <2^24)

// ---------------- zeroing ---------------------------------------------------
// flag ZERO_DEG: also zero the degree array (only needed once).
template <bool ZERO_DEG>
__global__ void k_zero() {
    int i = blockIdx.x * blockDim.x + threadIdx.x;
    int total4 = N_NODES * D / 4;
    if (i < total4) g_agg4[i] = make_float4(0.f, 0.f, 0.f, 0.f);
    if (ZERO_DEG) {
        // strided coverage of g_deg by the first N_NODES threads
        if (i < N_NODES) g_deg[i] = 0.f;
    }
}

// ---------------- degree ----------------------------------------------------
__global__ void k_deg(const int* __restrict__ dst) {
    int e = blockIdx.x * blockDim.x + threadIdx.x;
    if (e < N_EDGES) atomicAdd(&g_deg[dst[e]], 1.0f);
}

// ---------------- scatter: agg[dst] += feat[src] ----------------------------
// 16 threads per edge, one float4 each. FROM_H: read layer-1 hidden instead
// of the x input parameter.
template <bool FROM_H>
__global__ void k_scatter(const float* __restrict__ xin,
                          const int* __restrict__ src,
                          const int* __restrict__ dst) {
    long long t = (long long)blockIdx.x * blockDim.x + threadIdx.x;
    if (t >= (long long)N_EDGES * 16) return;
    int e = (int)(t >> 4);
    int q = (int)(t & 15);                     // float4 index within row
    int s = __ldg(&src[e]);
    int d = __ldg(&dst[e]);
    float4 v;
    if (FROM_H) v = g_h4[s * (D / 4) + q];
    else        v = __ldg((const float4*)(xin) + (long long)s * (D / 4) + q);
    atomicAdd(&g_agg4[d * (D / 4) + q], v);    // cc9.x vectorized red.v4.f32
}

// ---------------- fused SAGE layer -------------------------------------------
// out = selfX @ Wself + b + (agg/deg) @ Wneigh   (+ ReLU if RELU)
// Block: 256 threads handles 16 rows x 64 cols. Each thread owns one float4
// of output (row = tid>>4, quad = tid&15).
#define XPAD (D + 4)   // pad 4 floats: rows land 4 banks apart, 16B aligned

template <bool RELU, bool IN_IS_H, bool OUT_IS_H>
__global__ void __launch_bounds__(256, 5)
k_sage(const float* __restrict__ xin,
       const float* __restrict__ Wself,
       const float* __restrict__ Wneigh,
       const float* __restrict__ bias,
       float* __restrict__ out) {
    __shared__ float4 sWs[D][D / 4];   // [k][quad]  16 KB
    __shared__ float4 sWn[D][D / 4];   // 16 KB
    __shared__ float  sX[16][XPAD];    // self features   ~4.3 KB
    __shared__ float  sM[16][XPAD];    // mean features   ~4.3 KB

    int tid  = threadIdx.x;
    int row0 = blockIdx.x * 16;

    // stage weights (4096 floats each = 1024 float4 each)
    #pragma unroll 4
    for (int i = tid; i < D * D / 4; i += 256) {
        sWs[i >> 4][i & 15] = __ldg((const float4*)Wself  + i);
        sWn[i >> 4][i & 15] = __ldg((const float4*)Wneigh + i);
    }

    // stage self + mean tiles: 16 rows * 16 quads = 256 float4 -> 1 per thread
    {
        int r = tid >> 4;
        int q = tid & 15;
        int grow = row0 + r;
        float4 xv = make_float4(0.f, 0.f, 0.f, 0.f);
        float4 mv = xv;
        if (grow < N_NODES) {
            if (IN_IS_H) xv = g_h4[grow * (D / 4) + q];
            else         xv = __ldg((const float4*)xin + (long long)grow * (D / 4) + q);
            float dg  = g_deg[grow];
            float inv = 1.0f / fmaxf(dg, 1.0f);
            float4 a  = g_agg4[grow * (D / 4) + q];
            mv = make_float4(a.x * inv, a.y * inv, a.z * inv, a.w * inv);
        }
        *(float4*)&sX[r][q * 4] = xv;
        *(float4*)&sM[r][q * 4] = mv;
    }
    __syncthreads();

    int r = tid >> 4;        // 0..15
    int q = tid & 15;        // 0..15 (quad column)
    float4 acc = __ldg((const float4*)bias + q);

    #pragma unroll
    for (int k = 0; k < D; k++) {
        float  xv = sX[r][k];
        float  mv = sM[r][k];
        float4 ws = sWs[k][q];
        float4 wn = sWn[k][q];
        acc.x += xv * ws.x + mv * wn.x;
        acc.y += xv * ws.y + mv * wn.y;
        acc.z += xv * ws.z + mv * wn.z;
        acc.w += xv * ws.w + mv * wn.w;
    }

    if (RELU) {
        acc.x = fmaxf(acc.x, 0.f);
        acc.y = fmaxf(acc.y, 0.f);
        acc.z = fmaxf(acc.z, 0.f);
        acc.w = fmaxf(acc.w, 0.f);
    }

    int grow = row0 + r;
    if (grow < N_NODES) {
        if (OUT_IS_H) g_h4[grow * (D / 4) + q] = acc;
        else          *((float4*)out + (long long)grow * (D / 4) + q) = acc;
    }
}

// ---------------- launcher ---------------------------------------------------
extern "C" void kernel_launch(void* const* d_in, const int* in_sizes, int n_in,
                              void* d_out, int out_size) {
    const float* x       = (const float*)d_in[0];
    const int*   src     = (const int*)d_in[1];
    const int*   dst     = (const int*)d_in[2];
    const float* Wself1  = (const float*)d_in[3];
    const float* Wneigh1 = (const float*)d_in[4];
    const float* b1      = (const float*)d_in[5];
    const float* Wself2  = (const float*)d_in[6];
    const float* Wneigh2 = (const float*)d_in[7];
    const float* b2      = (const float*)d_in[8];
    float* out = (float*)d_out;

    const int ZBLK = 256;
    int zgrid = (N_NODES * D / 4 + ZBLK - 1) / ZBLK;
    int egrid = (N_EDGES + 255) / 256;
    long long sthreads = (long long)N_EDGES * 16;
    int sgrid = (int)((sthreads + 255) / 256);
    int ggrid = (N_NODES + 15) / 16;

    // layer 1
    k_zero<true><<<zgrid, ZBLK>>>();
    k_deg<<<egrid, 256>>>(dst);
    k_scatter<false><<<sgrid, 256>>>(x, src, dst);
    k_sage<true, false, true><<<ggrid, 256>>>(x, Wself1, Wneigh1, b1, nullptr);

    // layer 2
    k_zero<false><<<zgrid, ZBLK>>>();
    k_scatter<true><<<sgrid, 256>>>(nullptr, src, dst);
    k_sage<false, true, false><<<ggrid, 256>>>(nullptr, Wself2, Wneigh2, b2, out);
}

// round 2
// speedup vs baseline: 1.3473x; 1.3473x over previous
#include <cuda_runtime.h>

#define N_NODES 100000
#define N_EDGES 1000000
#define D 64

// ---------------- scratch (device globals; no runtime allocation) ----------
__device__ float4 g_agg4[N_NODES * D / 4];   // neighbor feature sums
__device__ float4 g_h4[N_NODES * D / 4];     // layer-1 hidden output
__device__ float  g_deg[N_NODES];            // in-degree

// ---------------- zeroing ---------------------------------------------------
template <bool ZERO_DEG>
__global__ void k_zero() {
    int i = blockIdx.x * blockDim.x + threadIdx.x;
    int total4 = N_NODES * D / 4;
    if (i < total4) g_agg4[i] = make_float4(0.f, 0.f, 0.f, 0.f);
    if (ZERO_DEG) {
        if (i < N_NODES) g_deg[i] = 0.f;
    }
}

// ---------------- degree ----------------------------------------------------
__global__ void k_deg(const int* __restrict__ dst) {
    int e = blockIdx.x * blockDim.x + threadIdx.x;
    if (e < N_EDGES) atomicAdd(&g_deg[dst[e]], 1.0f);
}

// ---------------- scatter: agg[dst] += feat[src] ----------------------------
// 16 threads per edge, one float4 each.
template <bool FROM_H>
__global__ void k_scatter(const float* __restrict__ xin,
                          const int* __restrict__ src,
                          const int* __restrict__ dst) {
    long long t = (long long)blockIdx.x * blockDim.x + threadIdx.x;
    if (t >= (long long)N_EDGES * 16) return;
    int e = (int)(t >> 4);
    int q = (int)(t & 15);
    int s = __ldg(&src[e]);
    int d = __ldg(&dst[e]);
    float4 v;
    if (FROM_H) v = g_h4[s * (D / 4) + q];
    else        v = __ldg((const float4*)(xin) + (long long)s * (D / 4) + q);
    atomicAdd(&g_agg4[d * (D / 4) + q], v);
}

// ---------------- fused SAGE layer -------------------------------------------
// out = selfX @ Wself + b + (agg/deg) @ Wneigh   (+ ReLU if RELU)
// Block = 256 threads -> 32-row x 64-col tile. Each thread: 2 rows x float4 cols.
// SMEM exactly 48 KB: Ws 16K + Wn 16K + X 8K + M 8K.
// 100000 % 32 == 0 -> no partial tiles, no guards in hot path.

#define TILE_R 32

template <bool RELU, bool IN_IS_H, bool OUT_IS_H>
__global__ void __launch_bounds__(256, 4)
k_sage(const float* __restrict__ xin,
       const float* __restrict__ Wself,
       const float* __restrict__ Wneigh,
       const float* __restrict__ bias,
       float* __restrict__ out) {
    __shared__ float4 sWs[D][16];        // [k][quad]   16 KB
    __shared__ float4 sWn[D][16];        // 16 KB
    __shared__ float4 sX[TILE_R][16];    // [row][k4]    8 KB (k-contiguous)
    __shared__ float4 sM[TILE_R][16];    //              8 KB

    int tid  = threadIdx.x;
    int q    = tid & 15;                 // output quad (cols 4q..4q+3)
    int row0 = blockIdx.x * TILE_R;

    // stage weights: D*16 = 1024 float4, 4 per thread
    #pragma unroll
    for (int i = tid; i < D * 16; i += 256) {
        sWs[i >> 4][i & 15] = __ldg((const float4*)Wself  + i);
        sWn[i >> 4][i & 15] = __ldg((const float4*)Wneigh + i);
    }

    // stage x + mean tiles: 32 rows * 16 quads = 512 float4, 2 per thread
    #pragma unroll
    for (int i = tid; i < TILE_R * 16; i += 256) {
        int r  = i >> 4;
        int qq = i & 15;
        int grow = row0 + r;
        float4 xv;
        if (IN_IS_H) xv = g_h4[grow * (D / 4) + qq];
        else         xv = __ldg((const float4*)xin + (long long)grow * (D / 4) + qq);
        float inv = 1.0f / fmaxf(g_deg[grow], 1.0f);
        float4 a  = g_agg4[grow * (D / 4) + qq];
        sX[r][qq] = xv;
        sM[r][qq] = make_float4(a.x * inv, a.y * inv, a.z * inv, a.w * inv);
    }
    __syncthreads();

    int r0 = (tid >> 4) * 2;             // 2 rows per thread
    float4 bq = __ldg((const float4*)bias + q);
    float4 acc0 = bq;
    float4 acc1 = bq;

#define SAGE_STEP(COMP, KIDX) do {                                  \
        float4 ws = sWs[KIDX][q];                                   \
        float4 wn = sWn[KIDX][q];                                   \
        acc0.x += xv0.COMP * ws.x + mv0.COMP * wn.x;                \
        acc0.y += xv0.COMP * ws.y + mv0.COMP * wn.y;                \
        acc0.z += xv0.COMP * ws.z + mv0.COMP * wn.z;                \
        acc0.w += xv0.COMP * ws.w + mv0.COMP * wn.w;                \
        acc1.x += xv1.COMP * ws.x + mv1.COMP * wn.x;                \
        acc1.y += xv1.COMP * ws.y + mv1.COMP * wn.y;                \
        acc1.z += xv1.COMP * ws.z + mv1.COMP * wn.z;                \
        acc1.w += xv1.COMP * ws.w + mv1.COMP * wn.w;                \
    } while (0)

    #pragma unroll 4
    for (int k4 = 0; k4 < 16; k4++) {
        float4 xv0 = sX[r0    ][k4];
        float4 mv0 = sM[r0    ][k4];
        float4 xv1 = sX[r0 + 1][k4];
        float4 mv1 = sM[r0 + 1][k4];
        int kb = k4 * 4;
        SAGE_STEP(x, kb + 0);
        SAGE_STEP(y, kb + 1);
        SAGE_STEP(z, kb + 2);
        SAGE_STEP(w, kb + 3);
    }
#undef SAGE_STEP

    if (RELU) {
        acc0.x = fmaxf(acc0.x, 0.f); acc0.y = fmaxf(acc0.y, 0.f);
        acc0.z = fmaxf(acc0.z, 0.f); acc0.w = fmaxf(acc0.w, 0.f);
        acc1.x = fmaxf(acc1.x, 0.f); acc1.y = fmaxf(acc1.y, 0.f);
        acc1.z = fmaxf(acc1.z, 0.f); acc1.w = fmaxf(acc1.w, 0.f);
    }

    int g0 = row0 + r0;
    if (OUT_IS_H) {
        g_h4[g0 * (D / 4) + q]       = acc0;
        g_h4[(g0 + 1) * (D / 4) + q] = acc1;
    } else {
        *((float4*)out + (long long)g0 * (D / 4) + q)       = acc0;
        *((float4*)out + (long long)(g0 + 1) * (D / 4) + q) = acc1;
    }
}

// ---------------- launcher ---------------------------------------------------
extern "C" void kernel_launch(void* const* d_in, const int* in_sizes, int n_in,
                              void* d_out, int out_size) {
    const float* x       = (const float*)d_in[0];
    const int*   src     = (const int*)d_in[1];
    const int*   dst     = (const int*)d_in[2];
    const float* Wself1  = (const float*)d_in[3];
    const float* Wneigh1 = (const float*)d_in[4];
    const float* b1      = (const float*)d_in[5];
    const float* Wself2  = (const float*)d_in[6];
    const float* Wneigh2 = (const float*)d_in[7];
    const float* b2      = (const float*)d_in[8];
    float* out = (float*)d_out;

    const int ZBLK = 256;
    int zgrid = (N_NODES * D / 4 + ZBLK - 1) / ZBLK;
    int egrid = (N_EDGES + 255) / 256;
    long long sthreads = (long long)N_EDGES * 16;
    int sgrid = (int)((sthreads + 255) / 256);
    int ggrid = N_NODES / TILE_R;          // 3125, exact

    // layer 1
    k_zero<true><<<zgrid, ZBLK>>>();
    k_deg<<<egrid, 256>>>(dst);
    k_scatter<false><<<sgrid, 256>>>(x, src, dst);
    k_sage<true, false, true><<<ggrid, 256>>>(x, Wself1, Wneigh1, b1, nullptr);

    // layer 2
    k_zero<false><<<zgrid, ZBLK>>>();
    k_scatter<true><<<sgrid, 256>>>(nullptr, src, dst);
    k_sage<false, true, false><<<ggrid, 256>>>(nullptr, Wself2, Wneigh2, b2, out);
}

// round 3
// speedup vs baseline: 1.3558x; 1.0063x over previous
#include <cuda_runtime.h>
#include <cstdint>

#define N_NODES 100000
#define N_EDGES 1000000
#define D 64
#define TILE_R 64
#define XPAD 65   // row stride (floats) for feature tiles: (row*65+k)%32 distinct per lane

// ---------------- scratch (device globals; no runtime allocation) ----------
__device__ float4 g_agg4[N_NODES * 16];   // neighbor feature sums
__device__ float4 g_h4[N_NODES * 16];     // layer-1 hidden output
__device__ float  g_deg[N_NODES];         // in-degree

// ---------------- packed fp32x2 helpers (sm_10x) -----------------------------
__device__ __forceinline__ uint64_t fma2(uint64_t a, uint64_t b, uint64_t c) {
    uint64_t d;
    asm("fma.rn.f32x2 %0, %1, %2, %3;" : "=l"(d) : "l"(a), "l"(b), "l"(c));
    return d;
}
__device__ __forceinline__ uint64_t pack2(float lo, float hi) {
    uint64_t d;
    asm("mov.b64 %0, {%1, %2};" : "=l"(d) : "f"(lo), "f"(hi));
    return d;
}
__device__ __forceinline__ void unpack2(uint64_t v, float& lo, float& hi) {
    asm("mov.b64 {%0, %1}, %2;" : "=f"(lo), "=f"(hi) : "l"(v));
}

// ---------------- zeroing ---------------------------------------------------
template <bool ZERO_DEG>
__global__ void k_zero() {
    int i = blockIdx.x * blockDim.x + threadIdx.x;
    int total4 = N_NODES * 16;
    if (i < total4) g_agg4[i] = make_float4(0.f, 0.f, 0.f, 0.f);
    if (ZERO_DEG) {
        if (i < N_NODES) g_deg[i] = 0.f;
    }
}

// ---------------- degree ----------------------------------------------------
__global__ void k_deg(const int* __restrict__ dst) {
    int e = blockIdx.x * blockDim.x + threadIdx.x;
    if (e < N_EDGES) atomicAdd(&g_deg[dst[e]], 1.0f);
}

// ---------------- scatter: agg[dst] += feat[src] ----------------------------
// 16 threads per edge, one float4 each; half-warp = one full coalesced row.
template <bool FROM_H>
__global__ void k_scatter(const float* __restrict__ xin,
                          const int* __restrict__ src,
                          const int* __restrict__ dst) {
    long long t = (long long)blockIdx.x * blockDim.x + threadIdx.x;
    if (t >= (long long)N_EDGES * 16) return;
    int e = (int)(t >> 4);
    int q = (int)(t & 15);
    int s = __ldg(&src[e]);
    int d = __ldg(&dst[e]);
    float4 v;
    if (FROM_H) v = g_h4[s * 16 + q];
    else        v = __ldg((const float4*)(xin) + (long long)s * 16 + q);
    atomicAdd(&g_agg4[d * 16 + q], v);
}

// ---------------- fused SAGE layer -------------------------------------------
// out = selfX @ Wself + b + (agg/deg) @ Wneigh   (+ ReLU)
// Block 256 thr = 8 warps; tile 64 rows x 64 cols.
// Warp w: rows rh*32..+31 (rh = w>>2, lane = row), cols cg*16..+15 (cg = w&3).
// Per k: scalar conflict-free LDS for x/m, broadcast LDS.128 for weights,
// 16 packed fma.f32x2 (= 32 FFMA-equiv).
template <bool RELU, bool IN_IS_H, bool OUT_IS_H>
__global__ void __launch_bounds__(256, 3)
k_sage(const float* __restrict__ xin,
       const float* __restrict__ Wself,
       const float* __restrict__ Wneigh,
       const float* __restrict__ bias,
       float* __restrict__ out) {
    extern __shared__ float smem[];
    float4* sWs = (float4*)smem;                       // [k*16 + c]  16 KB
    float4* sWn = (float4*)(smem + 4096);              // 16 KB
    float*  sX  = smem + 8192;                         // [row*XPAD + k] 16.6 KB
    float*  sM  = sX + TILE_R * XPAD;                  // 16.6 KB

    int tid  = threadIdx.x;
    int row0 = blockIdx.x * TILE_R;

    // stage weights: 1024 float4 each
    #pragma unroll
    for (int i = tid; i < 1024; i += 256) {
        sWs[i] = __ldg((const float4*)Wself  + i);
        sWn[i] = __ldg((const float4*)Wneigh + i);
    }

    // stage features (scalar stores: XPAD=65 keeps compute loads conflict-free)
    #pragma unroll
    for (int i = tid; i < TILE_R * 16; i += 256) {
        int r = i >> 4, q = i & 15;
        int grow = row0 + r;
        if (grow >= N_NODES) grow = N_NODES - 1;   // duplicate row; store guarded
        float4 xv;
        if (IN_IS_H) xv = g_h4[grow * 16 + q];
        else         xv = __ldg((const float4*)xin + (long long)grow * 16 + q);
        float  inv = 1.0f / fmaxf(g_deg[grow], 1.0f);
        float4 a   = g_agg4[grow * 16 + q];
        float* px = &sX[r * XPAD + q * 4];
        px[0] = xv.x; px[1] = xv.y; px[2] = xv.z; px[3] = xv.w;
        float* pm = &sM[r * XPAD + q * 4];
        pm[0] = a.x * inv; pm[1] = a.y * inv; pm[2] = a.z * inv; pm[3] = a.w * inv;
    }
    __syncthreads();

    int w    = tid >> 5;
    int lane = tid & 31;
    int rh   = w >> 2;            // 0..1
    int cg   = w & 3;             // 0..3
    int row  = rh * 32 + lane;
    const float* xrow = &sX[row * XPAD];
    const float* mrow = &sM[row * XPAD];

    uint64_t acc[8];
    #pragma unroll
    for (int j = 0; j < 8; j++) {
        float b0 = __ldg(bias + cg * 16 + j * 2);
        float b1 = __ldg(bias + cg * 16 + j * 2 + 1);
        acc[j] = pack2(b0, b1);
    }

    #pragma unroll 4
    for (int k = 0; k < D; k++) {
        float xv = xrow[k];
        float mv = mrow[k];
        uint64_t xv2 = pack2(xv, xv);
        uint64_t mv2 = pack2(mv, mv);
        const ulonglong2* wsr = (const ulonglong2*)&sWs[k * 16 + cg * 4];
        const ulonglong2* wnr = (const ulonglong2*)&sWn[k * 16 + cg * 4];
        #pragma unroll
        for (int j = 0; j < 4; j++) {
            ulonglong2 ws = wsr[j];
            ulonglong2 wn = wnr[j];
            acc[2 * j]     = fma2(xv2, ws.x, acc[2 * j]);
            acc[2 * j]     = fma2(mv2, wn.x, acc[2 * j]);
            acc[2 * j + 1] = fma2(xv2, ws.y, acc[2 * j + 1]);
            acc[2 * j + 1] = fma2(mv2, wn.y, acc[2 * j + 1]);
        }
    }

    int grow = row0 + row;
    if (grow < N_NODES) {
        #pragma unroll
        for (int j = 0; j < 4; j++) {
            float a0, a1, a2, a3;
            unpack2(acc[2 * j],     a0, a1);
            unpack2(acc[2 * j + 1], a2, a3);
            if (RELU) {
                a0 = fmaxf(a0, 0.f); a1 = fmaxf(a1, 0.f);
                a2 = fmaxf(a2, 0.f); a3 = fmaxf(a3, 0.f);
            }
            float4 v = make_float4(a0, a1, a2, a3);
            if (OUT_IS_H) g_h4[grow * 16 + cg * 4 + j] = v;
            else          *((float4*)out + (long long)grow * 16 + cg * 4 + j) = v;
        }
    }
}

// ---------------- launcher ---------------------------------------------------
#define SAGE_SMEM ((8192 + 2 * TILE_R * XPAD) * 4)   // 66048 bytes

extern "C" void kernel_launch(void* const* d_in, const int* in_sizes, int n_in,
                              void* d_out, int out_size) {
    const float* x       = (const float*)d_in[0];
    const int*   src     = (const int*)d_in[1];
    const int*   dst     = (const int*)d_in[2];
    const float* Wself1  = (const float*)d_in[3];
    const float* Wneigh1 = (const float*)d_in[4];
    const float* b1      = (const float*)d_in[5];
    const float* Wself2  = (const float*)d_in[6];
    const float* Wneigh2 = (const float*)d_in[7];
    const float* b2      = (const float*)d_in[8];
    float* out = (float*)d_out;

    // >48KB dynamic smem: set once on the (uncaptured) correctness call; persists.
    cudaFuncSetAttribute(k_sage<true, false, true>,
                         cudaFuncAttributeMaxDynamicSharedMemorySize, SAGE_SMEM);
    cudaFuncSetAttribute(k_sage<false, true, false>,
                         cudaFuncAttributeMaxDynamicSharedMemorySize, SAGE_SMEM);

    const int ZBLK = 256;
    int zgrid = (N_NODES * 16 + ZBLK - 1) / ZBLK;
    int egrid = (N_EDGES + 255) / 256;
    long long sthreads = (long long)N_EDGES * 16;
    int sgrid = (int)((sthreads + 255) / 256);
    int ggrid = (N_NODES + TILE_R - 1) / TILE_R;   // 1563

    // layer 1
    k_zero<true><<<zgrid, ZBLK>>>();
    k_deg<<<egrid, 256>>>(dst);
    k_scatter<false><<<sgrid, 256>>>(x, src, dst);
    k_sage<true, false, true><<<ggrid, 256, SAGE_SMEM>>>(x, Wself1, Wneigh1, b1, nullptr);

    // layer 2
    k_zero<false><<<zgrid, ZBLK>>>();
    k_scatter<true><<<sgrid, 256>>>(nullptr, src, dst);
    k_sage<false, true, false><<<ggrid, 256, SAGE_SMEM>>>(nullptr, Wself2, Wneigh2, b2, out);
}

// round 4
// speedup vs baseline: 1.5678x; 1.1564x over previous
#include <cuda_runtime.h>
#include <cstdint>

#define N_NODES 100000
#define N_EDGES 1000000
#define D 64
#define TILE_R 64
#define FSTRIDE 66                      // floats per k-row of a feature tile (even -> 8B aligned pairs)
#define SAGE_SMEM_FLOATS (8192 + 2 * D * FSTRIDE)   // 8192 weights + 2 feature tiles
#define SAGE_SMEM (SAGE_SMEM_FLOATS * 4)            // 66560 bytes

// ---------------- scratch (device globals; no runtime allocation) ----------
__device__ float4 g_agg4[N_NODES * 16];   // neighbor feature sums
__device__ float4 g_h4[N_NODES * 16];     // layer-1 hidden output
__device__ float  g_deg[N_NODES];         // in-degree

// ---------------- packed fp32x2 helpers (sm_10x) -----------------------------
__device__ __forceinline__ unsigned long long fma2(unsigned long long a,
                                                   unsigned long long b,
                                                   unsigned long long c) {
    unsigned long long d;
    asm("fma.rn.f32x2 %0, %1, %2, %3;" : "=l"(d) : "l"(a), "l"(b), "l"(c));
    return d;
}
__device__ __forceinline__ unsigned long long add2(unsigned long long a,
                                                   unsigned long long b) {
    unsigned long long d;
    asm("add.rn.f32x2 %0, %1, %2;" : "=l"(d) : "l"(a), "l"(b));
    return d;
}
__device__ __forceinline__ unsigned long long pack2(float lo, float hi) {
    unsigned long long d;
    asm("mov.b64 %0, {%1, %2};" : "=l"(d) : "f"(lo), "f"(hi));
    return d;
}
__device__ __forceinline__ void unpack2(unsigned long long v, float& lo, float& hi) {
    asm("mov.b64 {%0, %1}, %2;" : "=f"(lo), "=f"(hi) : "l"(v));
}

// ---------------- zeroing ---------------------------------------------------
template <bool ZERO_DEG>
__global__ void k_zero() {
    int i = blockIdx.x * blockDim.x + threadIdx.x;
    int total4 = N_NODES * 16;
    if (i < total4) g_agg4[i] = make_float4(0.f, 0.f, 0.f, 0.f);
    if (ZERO_DEG) {
        if (i < N_NODES) g_deg[i] = 0.f;
    }
}

// ---------------- degree ----------------------------------------------------
__global__ void k_deg(const int* __restrict__ dst) {
    int e = blockIdx.x * blockDim.x + threadIdx.x;
    if (e < N_EDGES) atomicAdd(&g_deg[dst[e]], 1.0f);
}

// ---------------- scatter: agg[dst] += feat[src] ----------------------------
template <bool FROM_H>
__global__ void k_scatter(const float* __restrict__ xin,
                          const int* __restrict__ src,
                          const int* __restrict__ dst) {
    long long t = (long long)blockIdx.x * blockDim.x + threadIdx.x;
    if (t >= (long long)N_EDGES * 16) return;
    int e = (int)(t >> 4);
    int q = (int)(t & 15);
    int s = __ldg(&src[e]);
    int d = __ldg(&dst[e]);
    float4 v;
    if (FROM_H) v = g_h4[s * 16 + q];
    else        v = __ldg((const float4*)(xin) + (long long)s * 16 + q);
    atomicAdd(&g_agg4[d * 16 + q], v);
}

// ---------------- fused SAGE layer -------------------------------------------
// out = selfX @ Wself + b + (agg/deg) @ Wneigh   (+ ReLU)
// Block 256 = 8 warps. Tile 64 rows x 64 cols. Warp w: rows w*8..w*8+7, all cols.
// Lane split: lanes 0-15 (hf=0) compute the Wself partial for quad j=lane,
//             lanes 16-31 (hf=1) compute the Wneigh partial for quad j=lane-16.
// Per k per warp: 1 LDS.128 weights (512B, zero redundancy) + 4 LDS.64 feature
// row-pairs (16-lane broadcast) + 16 fma.rn.f32x2 (rows packed in the 64-bit lane).
// Halves combined once at the end with shfl.xor(16) + add.f32x2.
template <bool RELU, bool IN_IS_H, bool OUT_IS_H>
__global__ void __launch_bounds__(256, 3)
k_sage(const float* __restrict__ xin,
       const float* __restrict__ Wself,
       const float* __restrict__ Wneigh,
       const float* __restrict__ bias,
       float* __restrict__ out) {
    extern __shared__ float smem[];
    float* sW  = smem;                    // [k*128 + quad*4 + j], quads 0-15 Ws, 16-31 Wn
    float* sXk = smem + 8192;             // [k*FSTRIDE + row]  (k-major!)
    float* sMk = sXk + D * FSTRIDE;

    int tid  = threadIdx.x;
    int row0 = blockIdx.x * TILE_R;

    // stage weights: 1024 float4 each; sW row k = 512B (Ws cols | Wn cols)
    #pragma unroll
    for (int i = tid; i < 1024; i += 256) {
        int k = i >> 4, q = i & 15;
        ((float4*)sW)[k * 32 + q]      = __ldg((const float4*)Wself  + i);
        ((float4*)sW)[k * 32 + 16 + q] = __ldg((const float4*)Wneigh + i);
    }

    // stage features K-MAJOR: sXk[k][r] = x[row0+r][k], sMk[k][r] = mean
    #pragma unroll
    for (int i = tid; i < TILE_R * 16; i += 256) {
        int r = i >> 4, q = i & 15;
        int grow = row0 + r;
        if (grow >= N_NODES) grow = N_NODES - 1;   // clamp; stores are guarded
        float4 xv;
        if (IN_IS_H) xv = g_h4[grow * 16 + q];
        else         xv = __ldg((const float4*)xin + (long long)grow * 16 + q);
        float  inv = 1.0f / fmaxf(g_deg[grow], 1.0f);
        float4 a   = g_agg4[grow * 16 + q];
        int kb = q * 4;
        sXk[(kb + 0) * FSTRIDE + r] = xv.x;
        sXk[(kb + 1) * FSTRIDE + r] = xv.y;
        sXk[(kb + 2) * FSTRIDE + r] = xv.z;
        sXk[(kb + 3) * FSTRIDE + r] = xv.w;
        sMk[(kb + 0) * FSTRIDE + r] = a.x * inv;
        sMk[(kb + 1) * FSTRIDE + r] = a.y * inv;
        sMk[(kb + 2) * FSTRIDE + r] = a.z * inv;
        sMk[(kb + 3) * FSTRIDE + r] = a.w * inv;
    }
    __syncthreads();

    int w     = tid >> 5;
    int lane  = tid & 31;
    int hf    = lane >> 4;                 // 0: x/Ws half, 1: m/Wn half
    int j     = lane & 15;                 // output quad (cols 4j..4j+3)
    int rbase = w * 8;                     // 8 rows per warp

    const float* feat = hf ? sMk : sXk;

    // acc[p][c]: rows (2p, 2p+1) packed in u64, col 4j+c
    unsigned long long acc[4][4];
    {
        float b0 = __ldg(bias + 4 * j + 0);
        float b1 = __ldg(bias + 4 * j + 1);
        float b2 = __ldg(bias + 4 * j + 2);
        float b3 = __ldg(bias + 4 * j + 3);
        unsigned long long bi[4] = { pack2(b0, b0), pack2(b1, b1),
                                     pack2(b2, b2), pack2(b3, b3) };
        #pragma unroll
        for (int p = 0; p < 4; p++)
            #pragma unroll
            for (int c = 0; c < 4; c++)
                acc[p][c] = hf ? 0ULL : bi[c];
    }

    #pragma unroll 4
    for (int k = 0; k < D; k++) {
        // weights: one LDS.128 per warp, all 32 lanes distinct (512B)
        float4 wq = ((const float4*)sW)[k * 32 + lane];
        unsigned long long w2[4] = { pack2(wq.x, wq.x), pack2(wq.y, wq.y),
                                     pack2(wq.z, wq.z), pack2(wq.w, wq.w) };
        // features: 4 row-pair LDS.64, broadcast within each 16-lane half
        const float* fk = &feat[k * FSTRIDE + rbase];
        unsigned long long f2[4];
        #pragma unroll
        for (int p = 0; p < 4; p++)
            f2[p] = *(const unsigned long long*)(fk + 2 * p);
        #pragma unroll
        for (int p = 0; p < 4; p++)
            #pragma unroll
            for (int c = 0; c < 4; c++)
                acc[p][c] = fma2(f2[p], w2[c], acc[p][c]);
    }

    // combine the two matrix halves: total = lo-half + hi-half
    #pragma unroll
    for (int p = 0; p < 4; p++)
        #pragma unroll
        for (int c = 0; c < 4; c++) {
            unsigned long long other =
                __shfl_xor_sync(0xffffffffu, acc[p][c], 16);
            acc[p][c] = add2(acc[p][c], other);
        }

    // store: hf=0 stores row-pairs p=0,1; hf=1 stores p=2,3
    int pstart = hf * 2;
    #pragma unroll
    for (int p = pstart; p < pstart + 2; p++) {
        float l0, h0, l1, h1, l2, h2, l3, h3;
        unpack2(acc[p][0], l0, h0);
        unpack2(acc[p][1], l1, h1);
        unpack2(acc[p][2], l2, h2);
        unpack2(acc[p][3], l3, h3);
        if (RELU) {
            l0 = fmaxf(l0, 0.f); h0 = fmaxf(h0, 0.f);
            l1 = fmaxf(l1, 0.f); h1 = fmaxf(h1, 0.f);
            l2 = fmaxf(l2, 0.f); h2 = fmaxf(h2, 0.f);
            l3 = fmaxf(l3, 0.f); h3 = fmaxf(h3, 0.f);
        }
        float4 v0 = make_float4(l0, l1, l2, l3);   // row 2p
        float4 v1 = make_float4(h0, h1, h2, h3);   // row 2p+1
        int g0 = row0 + rbase + 2 * p;
        if (g0 < N_NODES) {
            if (OUT_IS_H) g_h4[g0 * 16 + j] = v0;
            else          *((float4*)out + (long long)g0 * 16 + j) = v0;
        }
        if (g0 + 1 < N_NODES) {
            if (OUT_IS_H) g_h4[(g0 + 1) * 16 + j] = v1;
            else          *((float4*)out + (long long)(g0 + 1) * 16 + j) = v1;
        }
    }
}

// ---------------- launcher ---------------------------------------------------
extern "C" void kernel_launch(void* const* d_in, const int* in_sizes, int n_in,
                              void* d_out, int out_size) {
    const float* x       = (const float*)d_in[0];
    const int*   src     = (const int*)d_in[1];
    const int*   dst     = (const int*)d_in[2];
    const float* Wself1  = (const float*)d_in[3];
    const float* Wneigh1 = (const float*)d_in[4];
    const float* b1      = (const float*)d_in[5];
    const float* Wself2  = (const float*)d_in[6];
    const float* Wneigh2 = (const float*)d_in[7];
    const float* b2      = (const float*)d_in[8];
    float* out = (float*)d_out;

    // >48KB dynamic smem (set on the uncaptured correctness call; persists)
    cudaFuncSetAttribute(k_sage<true, false, true>,
                         cudaFuncAttributeMaxDynamicSharedMemorySize, SAGE_SMEM);
    cudaFuncSetAttribute(k_sage<false, true, false>,
                         cudaFuncAttributeMaxDynamicSharedMemorySize, SAGE_SMEM);

    const int ZBLK = 256;
    int zgrid = (N_NODES * 16 + ZBLK - 1) / ZBLK;
    int egrid = (N_EDGES + 255) / 256;
    long long sthreads = (long long)N_EDGES * 16;
    int sgrid = (int)((sthreads + 255) / 256);
    int ggrid = (N_NODES + TILE_R - 1) / TILE_R;   // 1563

    // layer 1
    k_zero<true><<<zgrid, ZBLK>>>();
    k_deg<<<egrid, 256>>>(dst);
    k_scatter<false><<<sgrid, 256>>>(x, src, dst);
    k_sage<true, false, true><<<ggrid, 256, SAGE_SMEM>>>(x, Wself1, Wneigh1, b1, nullptr);

    // layer 2
    k_zero<false><<<zgrid, ZBLK>>>();
    k_scatter<true><<<sgrid, 256>>>(nullptr, src, dst);
    k_sage<false, true, false><<<ggrid, 256, SAGE_SMEM>>>(nullptr, Wself2, Wneigh2, b2, out);
}

// round 5
// speedup vs baseline: 2.0392x; 1.3006x over previous
#include <cuda_runtime.h>
#include <cstdint>

#define N_NODES 100000
#define N_EDGES 1000000
#define D 64
#define TILE_R 64
#define FSTRIDE 66
#define SAGE_SMEM_FLOATS (8192 + 2 * D * FSTRIDE)
#define SAGE_SMEM (SAGE_SMEM_FLOATS * 4)            // 66560 bytes
#define NB_SCAN ((N_NODES + 255) / 256)             // 391 scan blocks

// ---------------- scratch (device globals) -----------------------------------
__device__ float4 g_agg4[N_NODES * 16];   // neighbor feature MEANS
__device__ float4 g_h4[N_NODES * 16];     // layer-1 hidden output
__device__ int    g_row[N_NODES + 1];     // CSR row pointers (by dst)
__device__ int    g_cur[N_NODES];         // counts, then fill cursors
__device__ int    g_csr[N_EDGES];         // src ids grouped by dst
__device__ int    g_bsum[512];            // scan block sums

// ---------------- packed fp32x2 helpers (sm_10x) -----------------------------
__device__ __forceinline__ unsigned long long fma2(unsigned long long a,
                                                   unsigned long long b,
                                                   unsigned long long c) {
    unsigned long long d;
    asm("fma.rn.f32x2 %0, %1, %2, %3;" : "=l"(d) : "l"(a), "l"(b), "l"(c));
    return d;
}
__device__ __forceinline__ unsigned long long add2(unsigned long long a,
                                                   unsigned long long b) {
    unsigned long long d;
    asm("add.rn.f32x2 %0, %1, %2;" : "=l"(d) : "l"(a), "l"(b));
    return d;
}
__device__ __forceinline__ unsigned long long pack2(float lo, float hi) {
    unsigned long long d;
    asm("mov.b64 %0, {%1, %2};" : "=l"(d) : "f"(lo), "f"(hi));
    return d;
}
__device__ __forceinline__ void unpack2(unsigned long long v, float& lo, float& hi) {
    asm("mov.b64 {%0, %1}, %2;" : "=f"(lo), "=f"(hi) : "l"(v));
}

// ================= CSR build ==================================================
__global__ void k_cnt_zero() {
    int i = blockIdx.x * blockDim.x + threadIdx.x;
    if (i < N_NODES) g_cur[i] = 0;
}

__global__ void k_hist(const int* __restrict__ dst) {
    int e = blockIdx.x * blockDim.x + threadIdx.x;
    if (e < N_EDGES) atomicAdd(&g_cur[dst[e]], 1);
}

// per-block exclusive scan of counts -> g_row, block totals -> g_bsum
__global__ void k_scan_block() {
    __shared__ int sh[256];
    int t = threadIdx.x;
    int i = blockIdx.x * 256 + t;
    int c = (i < N_NODES) ? g_cur[i] : 0;
    sh[t] = c;
    __syncthreads();
    #pragma unroll
    for (int off = 1; off < 256; off <<= 1) {
        int v = (t >= off) ? sh[t - off] : 0;
        __syncthreads();
        sh[t] += v;
        __syncthreads();
    }
    if (i < N_NODES) g_row[i] = sh[t] - c;   // exclusive
    if (t == 255) g_bsum[blockIdx.x] = sh[t];
}

// single block: exclusive scan of the 391 block sums (in place)
__global__ void k_scan_tops() {
    __shared__ int sh[512];
    int t = threadIdx.x;
    int c = (t < NB_SCAN) ? g_bsum[t] : 0;
    sh[t] = c;
    __syncthreads();
    #pragma unroll
    for (int off = 1; off < 512; off <<= 1) {
        int v = (t >= off) ? sh[t - off] : 0;
        __syncthreads();
        sh[t] += v;
        __syncthreads();
    }
    if (t < NB_SCAN) g_bsum[t] = sh[t] - c;  // exclusive
}

// add block offsets; init cursors
__global__ void k_scan_add() {
    int i = blockIdx.x * blockDim.x + threadIdx.x;
    if (i < N_NODES) {
        int v = g_row[i] + g_bsum[i >> 8];
        g_row[i] = v;
        g_cur[i] = v;
    }
    if (i == 0) g_row[N_NODES] = N_EDGES;
}

__global__ void k_fill(const int* __restrict__ src, const int* __restrict__ dst) {
    int e = blockIdx.x * blockDim.x + threadIdx.x;
    if (e < N_EDGES) {
        int pos = atomicAdd(&g_cur[dst[e]], 1);
        g_csr[pos] = src[e];
    }
}

// ================= gather-mean: agg[n] = mean_{s in N(n)} feat[s] =============
// One warp per node; half-warp per edge (lane q = quad, h = edge parity).
template <bool FROM_H>
__global__ void __launch_bounds__(256)
k_gather(const float* __restrict__ xin) {
    int wid = (blockIdx.x * blockDim.x + threadIdx.x) >> 5;
    if (wid >= N_NODES) return;
    int lane = threadIdx.x & 31;
    int q = lane & 15;
    int h = lane >> 4;
    int beg = __ldg(&g_row[wid]);
    int end = __ldg(&g_row[wid + 1]);

    float4 acc = make_float4(0.f, 0.f, 0.f, 0.f);
    for (int e = beg + h; e < end; e += 2) {
        int s = __ldg(&g_csr[e]);
        float4 v;
        if (FROM_H) v = g_h4[s * 16 + q];
        else        v = __ldg((const float4*)xin + (long long)s * 16 + q);
        acc.x += v.x; acc.y += v.y; acc.z += v.z; acc.w += v.w;
    }
    // combine the two half-warp partials (quad q lives in lanes q and q+16)
    acc.x += __shfl_xor_sync(0xffffffffu, acc.x, 16);
    acc.y += __shfl_xor_sync(0xffffffffu, acc.y, 16);
    acc.z += __shfl_xor_sync(0xffffffffu, acc.z, 16);
    acc.w += __shfl_xor_sync(0xffffffffu, acc.w, 16);

    if (h == 0) {
        float inv = 1.0f / fmaxf((float)(end - beg), 1.0f);
        g_agg4[wid * 16 + q] = make_float4(acc.x * inv, acc.y * inv,
                                           acc.z * inv, acc.w * inv);
    }
}

// ================= fused SAGE layer ===========================================
// out = selfX @ Wself + b + mean @ Wneigh   (+ ReLU)  [mean pre-divided in g_agg4]
template <bool RELU, bool IN_IS_H, bool OUT_IS_H>
__global__ void __launch_bounds__(256, 3)
k_sage(const float* __restrict__ xin,
       const float* __restrict__ Wself,
       const float* __restrict__ Wneigh,
       const float* __restrict__ bias,
       float* __restrict__ out) {
    extern __shared__ float smem[];
    float* sW  = smem;                    // [k*128 + quad*4 + j]: quads 0-15 Ws, 16-31 Wn
    float* sXk = smem + 8192;             // [k*FSTRIDE + row]  (k-major)
    float* sMk = sXk + D * FSTRIDE;

    int tid  = threadIdx.x;
    int row0 = blockIdx.x * TILE_R;

    #pragma unroll
    for (int i = tid; i < 1024; i += 256) {
        int k = i >> 4, q = i & 15;
        ((float4*)sW)[k * 32 + q]      = __ldg((const float4*)Wself  + i);
        ((float4*)sW)[k * 32 + 16 + q] = __ldg((const float4*)Wneigh + i);
    }

    #pragma unroll
    for (int i = tid; i < TILE_R * 16; i += 256) {
        int r = i >> 4, q = i & 15;
        int grow = row0 + r;
        if (grow >= N_NODES) grow = N_NODES - 1;
        float4 xv;
        if (IN_IS_H) xv = g_h4[grow * 16 + q];
        else         xv = __ldg((const float4*)xin + (long long)grow * 16 + q);
        float4 a = g_agg4[grow * 16 + q];   // already the mean
        int kb = q * 4;
        sXk[(kb + 0) * FSTRIDE + r] = xv.x;
        sXk[(kb + 1) * FSTRIDE + r] = xv.y;
        sXk[(kb + 2) * FSTRIDE + r] = xv.z;
        sXk[(kb + 3) * FSTRIDE + r] = xv.w;
        sMk[(kb + 0) * FSTRIDE + r] = a.x;
        sMk[(kb + 1) * FSTRIDE + r] = a.y;
        sMk[(kb + 2) * FSTRIDE + r] = a.z;
        sMk[(kb + 3) * FSTRIDE + r] = a.w;
    }
    __syncthreads();

    int w     = tid >> 5;
    int lane  = tid & 31;
    int hf    = lane >> 4;
    int j     = lane & 15;
    int rbase = w * 8;

    const float* feat = hf ? sMk : sXk;

    unsigned long long acc[4][4];
    {
        float b0 = __ldg(bias + 4 * j + 0);
        float b1 = __ldg(bias + 4 * j + 1);
        float b2 = __ldg(bias + 4 * j + 2);
        float b3 = __ldg(bias + 4 * j + 3);
        unsigned long long bi[4] = { pack2(b0, b0), pack2(b1, b1),
                                     pack2(b2, b2), pack2(b3, b3) };
        #pragma unroll
        for (int p = 0; p < 4; p++)
            #pragma unroll
            for (int c = 0; c < 4; c++)
                acc[p][c] = hf ? 0ULL : bi[c];
    }

    #pragma unroll 4
    for (int k = 0; k < D; k++) {
        float4 wq = ((const float4*)sW)[k * 32 + lane];
        unsigned long long w2[4] = { pack2(wq.x, wq.x), pack2(wq.y, wq.y),
                                     pack2(wq.z, wq.z), pack2(wq.w, wq.w) };
        const float* fk = &feat[k * FSTRIDE + rbase];
        unsigned long long f2[4];
        #pragma unroll
        for (int p = 0; p < 4; p++)
            f2[p] = *(const unsigned long long*)(fk + 2 * p);
        #pragma unroll
        for (int p = 0; p < 4; p++)
            #pragma unroll
            for (int c = 0; c < 4; c++)
                acc[p][c] = fma2(f2[p], w2[c], acc[p][c]);
    }

    #pragma unroll
    for (int p = 0; p < 4; p++)
        #pragma unroll
        for (int c = 0; c < 4; c++) {
            unsigned long long other =
                __shfl_xor_sync(0xffffffffu, acc[p][c], 16);
            acc[p][c] = add2(acc[p][c], other);
        }

    int pstart = hf * 2;
    #pragma unroll
    for (int p = pstart; p < pstart + 2; p++) {
        float l0, h0, l1, h1, l2, h2, l3, h3;
        unpack2(acc[p][0], l0, h0);
        unpack2(acc[p][1], l1, h1);
        unpack2(acc[p][2], l2, h2);
        unpack2(acc[p][3], l3, h3);
        if (RELU) {
            l0 = fmaxf(l0, 0.f); h0 = fmaxf(h0, 0.f);
            l1 = fmaxf(l1, 0.f); h1 = fmaxf(h1, 0.f);
            l2 = fmaxf(l2, 0.f); h2 = fmaxf(h2, 0.f);
            l3 = fmaxf(l3, 0.f); h3 = fmaxf(h3, 0.f);
        }
        float4 v0 = make_float4(l0, l1, l2, l3);
        float4 v1 = make_float4(h0, h1, h2, h3);
        int g0 = row0 + rbase + 2 * p;
        if (g0 < N_NODES) {
            if (OUT_IS_H) g_h4[g0 * 16 + j] = v0;
            else          *((float4*)out + (long long)g0 * 16 + j) = v0;
        }
        if (g0 + 1 < N_NODES) {
            if (OUT_IS_H) g_h4[(g0 + 1) * 16 + j] = v1;
            else          *((float4*)out + (long long)(g0 + 1) * 16 + j) = v1;
        }
    }
}

// ---------------- launcher ---------------------------------------------------
extern "C" void kernel_launch(void* const* d_in, const int* in_sizes, int n_in,
                              void* d_out, int out_size) {
    const float* x       = (const float*)d_in[0];
    const int*   src     = (const int*)d_in[1];
    const int*   dst     = (const int*)d_in[2];
    const float* Wself1  = (const float*)d_in[3];
    const float* Wneigh1 = (const float*)d_in[4];
    const float* b1      = (const float*)d_in[5];
    const float* Wself2  = (const float*)d_in[6];
    const float* Wneigh2 = (const float*)d_in[7];
    const float* b2      = (const float*)d_in[8];
    float* out = (float*)d_out;

    cudaFuncSetAttribute(k_sage<true, false, true>,
                         cudaFuncAttributeMaxDynamicSharedMemorySize, SAGE_SMEM);
    cudaFuncSetAttribute(k_sage<false, true, false>,
                         cudaFuncAttributeMaxDynamicSharedMemorySize, SAGE_SMEM);

    int ngrid = (N_NODES + 255) / 256;      // 391
    int egrid = (N_EDGES + 255) / 256;      // 3907
    int wgrid = (N_NODES * 32 + 255) / 256; // 12500 (warp per node)
    int ggrid = (N_NODES + TILE_R - 1) / TILE_R;  // 1563

    // CSR build (per launch; deterministic work)
    k_cnt_zero<<<ngrid, 256>>>();
    k_hist<<<egrid, 256>>>(dst);
    k_scan_block<<<NB_SCAN, 256>>>();
    k_scan_tops<<<1, 512>>>();
    k_scan_add<<<ngrid, 256>>>();
    k_fill<<<egrid, 256>>>(src, dst);

    // layer 1
    k_gather<false><<<wgrid, 256>>>(x);
    k_sage<true, false, true><<<ggrid, 256, SAGE_SMEM>>>(x, Wself1, Wneigh1, b1, nullptr);

    // layer 2
    k_gather<true><<<wgrid, 256>>>(nullptr);
    k_sage<false, true, false><<<ggrid, 256, SAGE_SMEM>>>(nullptr, Wself2, Wneigh2, b2, out);
}

// round 6
// speedup vs baseline: 2.0429x; 1.0018x over previous
#include <cuda_runtime.h>
#include <cstdint>

#define N_NODES 100000
#define N_EDGES 1000000
#define D 64
#define TILE_R 128
#define FSTRIDE 130
#define SAGE_SMEM_FLOATS (8192 + 2 * D * FSTRIDE)   // 24832 floats
#define SAGE_SMEM (SAGE_SMEM_FLOATS * 4)            // 99328 bytes
#define NB_SCAN ((N_NODES + 255) / 256)             // 391 scan blocks

// ---------------- scratch (device globals) -----------------------------------
__device__ float4 g_agg4[N_NODES * 16];   // neighbor feature MEANS
__device__ float4 g_h4[N_NODES * 16];     // layer-1 hidden output
__device__ int    g_row[N_NODES + 1];     // CSR row pointers (by dst)
__device__ int    g_cur[N_NODES];         // counts, then fill cursors
__device__ int    g_csr[N_EDGES];         // src ids grouped by dst
__device__ int    g_bsum[512];            // scan block sums

// ---------------- packed fp32x2 helpers (sm_10x) -----------------------------
__device__ __forceinline__ unsigned long long fma2(unsigned long long a,
                                                   unsigned long long b,
                                                   unsigned long long c) {
    unsigned long long d;
    asm("fma.rn.f32x2 %0, %1, %2, %3;" : "=l"(d) : "l"(a), "l"(b), "l"(c));
    return d;
}
__device__ __forceinline__ unsigned long long add2(unsigned long long a,
                                                   unsigned long long b) {
    unsigned long long d;
    asm("add.rn.f32x2 %0, %1, %2;" : "=l"(d) : "l"(a), "l"(b));
    return d;
}
__device__ __forceinline__ unsigned long long pack2(float lo, float hi) {
    unsigned long long d;
    asm("mov.b64 %0, {%1, %2};" : "=l"(d) : "f"(lo), "f"(hi));
    return d;
}
__device__ __forceinline__ void unpack2(unsigned long long v, float& lo, float& hi) {
    asm("mov.b64 {%0, %1}, %2;" : "=f"(lo), "=f"(hi) : "l"(v));
}

// ================= CSR build ==================================================
__global__ void k_cnt_zero() {
    int i = blockIdx.x * blockDim.x + threadIdx.x;
    if (i < N_NODES) g_cur[i] = 0;
}

__global__ void k_hist(const int* __restrict__ dst) {
    int e = blockIdx.x * blockDim.x + threadIdx.x;
    if (e < N_EDGES) atomicAdd(&g_cur[dst[e]], 1);
}

// per-block exclusive scan of counts -> g_row, block totals -> g_bsum
__global__ void k_scan_block() {
    __shared__ int sh[256];
    int t = threadIdx.x;
    int i = blockIdx.x * 256 + t;
    int c = (i < N_NODES) ? g_cur[i] : 0;
    sh[t] = c;
    __syncthreads();
    #pragma unroll
    for (int off = 1; off < 256; off <<= 1) {
        int v = (t >= off) ? sh[t - off] : 0;
        __syncthreads();
        sh[t] += v;
        __syncthreads();
    }
    if (i < N_NODES) g_row[i] = sh[t] - c;   // exclusive
    if (t == 255) g_bsum[blockIdx.x] = sh[t];
}

// single WARP: exclusive scan of the 391 block sums in place (no block barriers)
#define SCAN_PER_LANE ((NB_SCAN + 31) / 32)   // 13
__global__ void k_scan_tops() {
    int lane = threadIdx.x;     // 32 threads
    int base = lane * SCAN_PER_LANE;
    int v[SCAN_PER_LANE];
    int sum = 0;
    #pragma unroll
    for (int i = 0; i < SCAN_PER_LANE; i++) {
        int idx = base + i;
        v[i] = (idx < NB_SCAN) ? g_bsum[idx] : 0;
        sum += v[i];
    }
    // exclusive shuffle scan of per-lane totals
    int pre = sum;
    #pragma unroll
    for (int off = 1; off < 32; off <<= 1) {
        int o = __shfl_up_sync(0xffffffffu, pre, off);
        if (lane >= off) pre += o;
    }
    pre -= sum;   // exclusive prefix of this lane's chunk
    #pragma unroll
    for (int i = 0; i < SCAN_PER_LANE; i++) {
        int idx = base + i;
        if (idx < NB_SCAN) g_bsum[idx] = pre;
        pre += v[i];
    }
}

// add block offsets; init cursors
__global__ void k_scan_add() {
    int i = blockIdx.x * blockDim.x + threadIdx.x;
    if (i < N_NODES) {
        int v = g_row[i] + g_bsum[i >> 8];
        g_row[i] = v;
        g_cur[i] = v;
    }
    if (i == 0) g_row[N_NODES] = N_EDGES;
}

__global__ void k_fill(const int* __restrict__ src, const int* __restrict__ dst) {
    int e = blockIdx.x * blockDim.x + threadIdx.x;
    if (e < N_EDGES) {
        int pos = atomicAdd(&g_cur[dst[e]], 1);
        g_csr[pos] = src[e];
    }
}

// ================= gather-mean: agg[n] = mean_{s in N(n)} feat[s] =============
template <bool FROM_H>
__global__ void __launch_bounds__(256)
k_gather(const float* __restrict__ xin) {
    int wid = (blockIdx.x * blockDim.x + threadIdx.x) >> 5;
    if (wid >= N_NODES) return;
    int lane = threadIdx.x & 31;
    int q = lane & 15;
    int h = lane >> 4;
    int beg = __ldg(&g_row[wid]);
    int end = __ldg(&g_row[wid + 1]);

    float4 acc = make_float4(0.f, 0.f, 0.f, 0.f);
    for (int e = beg + h; e < end; e += 2) {
        int s = __ldg(&g_csr[e]);
        float4 v;
        if (FROM_H) v = g_h4[s * 16 + q];
        else        v = __ldg((const float4*)xin + (long long)s * 16 + q);
        acc.x += v.x; acc.y += v.y; acc.z += v.z; acc.w += v.w;
    }
    acc.x += __shfl_xor_sync(0xffffffffu, acc.x, 16);
    acc.y += __shfl_xor_sync(0xffffffffu, acc.y, 16);
    acc.z += __shfl_xor_sync(0xffffffffu, acc.z, 16);
    acc.w += __shfl_xor_sync(0xffffffffu, acc.w, 16);

    if (h == 0) {
        float inv = 1.0f / fmaxf((float)(end - beg), 1.0f);
        g_agg4[wid * 16 + q] = make_float4(acc.x * inv, acc.y * inv,
                                           acc.z * inv, acc.w * inv);
    }
}

// ================= fused SAGE layer ===========================================
// out = selfX @ Wself + b + mean @ Wneigh (+ ReLU). Tile 128 rows x 64 cols.
// Block 256 = 8 warps; warp w: rows w*16..+15. Lanes 0-15 compute the Wself
// partial, lanes 16-31 the Wneigh partial; combined with shfl.xor(16).
// Per k per warp: 1 LDS.128 weights (512B) + 8 LDS.64 feature row-pairs
// (broadcast within half) + 32 fma.rn.f32x2 -> FMA-bound.
template <bool RELU, bool IN_IS_H, bool OUT_IS_H>
__global__ void __launch_bounds__(256, 2)
k_sage(const float* __restrict__ xin,
       const float* __restrict__ Wself,
       const float* __restrict__ Wneigh,
       const float* __restrict__ bias,
       float* __restrict__ out) {
    extern __shared__ float smem[];
    float* sW  = smem;                    // [k*128 + quad*4 + j]: quads 0-15 Ws, 16-31 Wn
    float* sXk = smem + 8192;             // [k*FSTRIDE + row] (k-major)
    float* sMk = sXk + D * FSTRIDE;

    int tid  = threadIdx.x;
    int row0 = blockIdx.x * TILE_R;

    #pragma unroll
    for (int i = tid; i < 1024; i += 256) {
        int k = i >> 4, q = i & 15;
        ((float4*)sW)[k * 32 + q]      = __ldg((const float4*)Wself  + i);
        ((float4*)sW)[k * 32 + 16 + q] = __ldg((const float4*)Wneigh + i);
    }

    #pragma unroll
    for (int i = tid; i < TILE_R * 16; i += 256) {
        int r = i >> 4, q = i & 15;
        int grow = row0 + r;
        if (grow >= N_NODES) grow = N_NODES - 1;   // clamp; stores guarded
        float4 xv;
        if (IN_IS_H) xv = g_h4[grow * 16 + q];
        else         xv = __ldg((const float4*)xin + (long long)grow * 16 + q);
        float4 a = g_agg4[grow * 16 + q];          // already the mean
        int kb = q * 4;
        sXk[(kb + 0) * FSTRIDE + r] = xv.x;
        sXk[(kb + 1) * FSTRIDE + r] = xv.y;
        sXk[(kb + 2) * FSTRIDE + r] = xv.z;
        sXk[(kb + 3) * FSTRIDE + r] = xv.w;
        sMk[(kb + 0) * FSTRIDE + r] = a.x;
        sMk[(kb + 1) * FSTRIDE + r] = a.y;
        sMk[(kb + 2) * FSTRIDE + r] = a.z;
        sMk[(kb + 3) * FSTRIDE + r] = a.w;
    }
    __syncthreads();

    int w     = tid >> 5;
    int lane  = tid & 31;
    int hf    = lane >> 4;                 // 0: x/Ws half, 1: m/Wn half
    int j     = lane & 15;                 // output quad
    int rbase = w * 16;                    // 16 rows per warp

    const float* feat = hf ? sMk : sXk;

    // acc[p][c]: rows (2p, 2p+1) packed in u64, col 4j+c
    unsigned long long acc[8][4];
    {
        float b0 = __ldg(bias + 4 * j + 0);
        float b1 = __ldg(bias + 4 * j + 1);
        float b2 = __ldg(bias + 4 * j + 2);
        float b3 = __ldg(bias + 4 * j + 3);
        unsigned long long bi[4] = { pack2(b0, b0), pack2(b1, b1),
                                     pack2(b2, b2), pack2(b3, b3) };
        #pragma unroll
        for (int p = 0; p < 8; p++)
            #pragma unroll
            for (int c = 0; c < 4; c++)
                acc[p][c] = hf ? 0ULL : bi[c];
    }

    #pragma unroll 2
    for (int k = 0; k < D; k++) {
        float4 wq = ((const float4*)sW)[k * 32 + lane];
        unsigned long long w2[4] = { pack2(wq.x, wq.x), pack2(wq.y, wq.y),
                                     pack2(wq.z, wq.z), pack2(wq.w, wq.w) };
        const float* fk = &feat[k * FSTRIDE + rbase];
        unsigned long long f2[8];
        #pragma unroll
        for (int p = 0; p < 8; p++)
            f2[p] = *(const unsigned long long*)(fk + 2 * p);
        #pragma unroll
        for (int p = 0; p < 8; p++)
            #pragma unroll
            for (int c = 0; c < 4; c++)
                acc[p][c] = fma2(f2[p], w2[c], acc[p][c]);
    }

    #pragma unroll
    for (int p = 0; p < 8; p++)
        #pragma unroll
        for (int c = 0; c < 4; c++) {
            unsigned long long other =
                __shfl_xor_sync(0xffffffffu, acc[p][c], 16);
            acc[p][c] = add2(acc[p][c], other);
        }

    // hf=0 stores row-pairs 0..3, hf=1 stores 4..7
    int pstart = hf * 4;
    #pragma unroll
    for (int p = pstart; p < pstart + 4; p++) {
        float l0, h0, l1, h1, l2, h2, l3, h3;
        unpack2(acc[p][0], l0, h0);
        unpack2(acc[p][1], l1, h1);
        unpack2(acc[p][2], l2, h2);
        unpack2(acc[p][3], l3, h3);
        if (RELU) {
            l0 = fmaxf(l0, 0.f); h0 = fmaxf(h0, 0.f);
            l1 = fmaxf(l1, 0.f); h1 = fmaxf(h1, 0.f);
            l2 = fmaxf(l2, 0.f); h2 = fmaxf(h2, 0.f);
            l3 = fmaxf(l3, 0.f); h3 = fmaxf(h3, 0.f);
        }
        float4 v0 = make_float4(l0, l1, l2, l3);   // row 2p
        float4 v1 = make_float4(h0, h1, h2, h3);   // row 2p+1
        int g0 = row0 + rbase + 2 * p;
        if (g0 < N_NODES) {
            if (OUT_IS_H) g_h4[g0 * 16 + j] = v0;
            else          *((float4*)out + (long long)g0 * 16 + j) = v0;
        }
        if (g0 + 1 < N_NODES) {
            if (OUT_IS_H) g_h4[(g0 + 1) * 16 + j] = v1;
            else          *((float4*)out + (long long)(g0 + 1) * 16 + j) = v1;
        }
    }
}

// ---------------- launcher ---------------------------------------------------
extern "C" void kernel_launch(void* const* d_in, const int* in_sizes, int n_in,
                              void* d_out, int out_size) {
    const float* x       = (const float*)d_in[0];
    const int*   src     = (const int*)d_in[1];
    const int*   dst     = (const int*)d_in[2];
    const float* Wself1  = (const float*)d_in[3];
    const float* Wneigh1 = (const float*)d_in[4];
    const float* b1      = (const float*)d_in[5];
    const float* Wself2  = (const float*)d_in[6];
    const float* Wneigh2 = (const float*)d_in[7];
    const float* b2      = (const float*)d_in[8];
    float* out = (float*)d_out;

    cudaFuncSetAttribute(k_sage<true, false, true>,
                         cudaFuncAttributeMaxDynamicSharedMemorySize, SAGE_SMEM);
    cudaFuncSetAttribute(k_sage<false, true, false>,
                         cudaFuncAttributeMaxDynamicSharedMemorySize, SAGE_SMEM);

    int ngrid = (N_NODES + 255) / 256;      // 391
    int egrid = (N_EDGES + 255) / 256;      // 3907
    int wgrid = (N_NODES * 32 + 255) / 256; // 12500 (warp per node)
    int ggrid = (N_NODES + TILE_R - 1) / TILE_R;  // 782

    // CSR build (per launch; deterministic work)
    k_cnt_zero<<<ngrid, 256>>>();
    k_hist<<<egrid, 256>>>(dst);
    k_scan_block<<<NB_SCAN, 256>>>();
    k_scan_tops<<<1, 32>>>();
    k_scan_add<<<ngrid, 256>>>();
    k_fill<<<egrid, 256>>>(src, dst);

    // layer 1
    k_gather<false><<<wgrid, 256>>>(x);
    k_sage<true, false, true><<<ggrid, 256, SAGE_SMEM>>>(x, Wself1, Wneigh1, b1, nullptr);

    // layer 2
    k_gather<true><<<wgrid, 256>>>(nullptr);
    k_sage<false, true, false><<<ggrid, 256, SAGE_SMEM>>>(nullptr, Wself2, Wneigh2, b2, out);
}